// round 15
// baseline (speedup 1.0000x reference)
#include <cuda_runtime.h>
#include <cuda_bf16.h>
#include <cuda_fp16.h>
#include <cstdint>

// ---------------- problem constants ----------------
#define TB      64          // batch
#define NCH     512         // hidden cells
#define TSTEPS  1024        // SY*SX
#define G4      2048        // 4*NCH gate columns
#define K_IH    560         // 48 + NCH
#define NCTA    128         // CTA (j,s): j = gate-col block (64), s = batch half (2)
#define THREADS 256         // 8 warps: rg=w&1 (16-row group), kq=w>>1 (K quarter)
#define HSTRIDE ((size_t)TSTEPS * NCH)
#define S_W     264         // smem words/col, fp16 pairs (==8 mod 32 -> conflict-free LDS.64)
#define S_X     48          // xc_k smem words/col
#define FPAD    32          // ints per flag: one 128B line each
#define RSL     32          // CTA-private ring slots
#define OFF_WPRE (32 * S_W)         // word offset: W_ihh weights
#define OFF_RED  (64 * S_W)         // word offset: partials (2 sets x 4096 floats)
#define SMEM_WORDS (OFF_RED + 8192)

// ---------------- device scratch (static: allocation-free) ----------------
__device__ float d_G[(size_t)TSTEPS * TB * G4];        // xc_k output (x@W_ihx + bias), 512 MB
__device__ uint4 d_Hq[(size_t)TSTEPS * TB * 128];      // h fp16 {hi2,hi2,lo2,lo2} per 4 cells
__device__ float d_R[(size_t)NCTA * RSL * 1024];       // CTA-private look-ahead rings, 16 MB
__device__ int   d_h_done[NCTA * FPAD];                // flag (s*64 + j)

// ---------------- bf16 helpers (xc_k only) ----------------
__device__ __forceinline__ uint32_t pack2b(float e0, float e1) {
    uint32_t d;
    asm("cvt.rn.bf16x2.f32 %0, %1, %2;" : "=r"(d) : "f"(e1), "f"(e0));
    return d;
}
__device__ __forceinline__ uint32_t lo_resb(uint32_t hp, float e0, float e1) {
    float h0 = __uint_as_float(hp << 16);
    float h1 = __uint_as_float(hp & 0xFFFF0000u);
    return pack2b(e0 - h0, e1 - h1);
}
__device__ __forceinline__ void mma16b(float* c,
                                       uint32_t a0, uint32_t a1, uint32_t a2, uint32_t a3,
                                       uint32_t b0, uint32_t b1) {
    asm volatile(
        "mma.sync.aligned.m16n8k16.row.col.f32.bf16.bf16.f32 "
        "{%0,%1,%2,%3},{%4,%5,%6,%7},{%8,%9},{%0,%1,%2,%3};"
        : "+f"(c[0]), "+f"(c[1]), "+f"(c[2]), "+f"(c[3])
        : "r"(a0), "r"(a1), "r"(a2), "r"(a3), "r"(b0), "r"(b1));
}

// ---------------- fp16 helpers ----------------
__device__ __forceinline__ uint32_t pack2h(float e0, float e1) {
    uint32_t d;
    asm("cvt.rn.f16x2.f32 %0, %1, %2;" : "=r"(d) : "f"(e1), "f"(e0));
    return d;
}
__device__ __forceinline__ uint32_t lo_resh(uint32_t hp, float e0, float e1) {
    __half2 h = *reinterpret_cast<__half2*>(&hp);
    float h0 = __half2float(__low2half(h));
    float h1 = __half2float(__high2half(h));
    return pack2h(e0 - h0, e1 - h1);
}
__device__ __forceinline__ void mma16h(float* c,
                                       uint32_t a0, uint32_t a1, uint32_t a2, uint32_t a3,
                                       uint32_t b0, uint32_t b1) {
    asm volatile(
        "mma.sync.aligned.m16n8k16.row.col.f32.f16.f16.f32 "
        "{%0,%1,%2,%3},{%4,%5,%6,%7},{%8,%9},{%0,%1,%2,%3};"
        : "+f"(c[0]), "+f"(c[1]), "+f"(c[2]), "+f"(c[3])
        : "r"(a0), "r"(a1), "r"(a2), "r"(a3), "r"(b0), "r"(b1));
}

__device__ __forceinline__ int ld_acq(const int* p) {
    int v;
    asm volatile("ld.acquire.gpu.global.b32 %0, [%1];" : "=r"(v) : "l"(p) : "memory");
    return v;
}
__device__ __forceinline__ void st_rel(int* p, int v) {
    asm volatile("st.release.gpu.global.b32 [%0], %1;" :: "l"(p), "r"(v) : "memory");
}
__device__ __forceinline__ float sigm(float x)  { return 1.0f / (1.0f + __expf(-x)); }
__device__ __forceinline__ float tanh_f(float x){ return 1.0f - 2.0f / (__expf(2.0f * x) + 1.0f); }

// ---------------- init (graph-replay safe) ----------------
__global__ void init_k() {
    int i = blockIdx.x * blockDim.x + threadIdx.x;
    if (i < NCTA * FPAD) d_h_done[i] = -1;
}

// ---------------- Xc precompute: G0[t] = bias + x_t @ W_ih[:, :48]^T ----------------
__global__ void __launch_bounds__(128)
xc_k(const float* __restrict__ batch, const float* __restrict__ W_ih,
     const float* __restrict__ b_ih, const float* __restrict__ b_hh) {
    __shared__ uint32_t sw[32 * S_X];
    const int tid = threadIdx.x;
    const int lane = tid & 31, w = tid >> 5;
    const int gid = lane >> 2, tig = lane & 3;
    const int row0 = w * 16 + gid, row1 = row0 + 8;
    const int gb = blockIdx.x * 32;

    for (int idx = tid; idx < 32 * 24; idx += 128) {
        int cl = idx / 24, k0 = (idx - cl * 24) * 2;
        float w0 = W_ih[(size_t)(gb + cl) * K_IH + k0];
        float w1 = W_ih[(size_t)(gb + cl) * K_IH + k0 + 1];
        uint32_t hi = pack2b(w0, w1);
        int kt = k0 >> 4, r = k0 & 15;
        int pos = cl * S_X + kt * 16 + (r >> 2) * 4 + ((r >> 1) & 1);
        sw[pos] = hi; sw[pos + 2] = lo_resb(hi, w0, w1);
    }
    __syncthreads();

    float bias[4][2];
#pragma unroll
    for (int nt = 0; nt < 4; nt++) {
        int g = gb + nt * 8 + tig * 2;
        bias[nt][0] = b_ih[g] + b_hh[g];
        bias[nt][1] = b_ih[g + 1] + b_hh[g + 1];
    }

    for (int us = 0; us < 64; us++) {
        const int u = blockIdx.y * 64 + us;
        const int i = u >> 5, j = u & 31;
        float acc[4][4];
#pragma unroll
        for (int nt = 0; nt < 4; nt++) {
            acc[nt][0] = bias[nt][0]; acc[nt][1] = bias[nt][1];
            acc[nt][2] = bias[nt][0]; acc[nt][3] = bias[nt][1];
        }
#pragma unroll
        for (int kt = 0; kt < 3; kt++) {
            float4 f0 = *(const float4*)&batch[(((size_t)row0 * 3 + kt) * 128 + i * 4 + tig) * 128 + j * 4];
            float4 f1 = *(const float4*)&batch[(((size_t)row1 * 3 + kt) * 128 + i * 4 + tig) * 128 + j * 4];
            uint32_t ah0 = pack2b(f0.x, f0.y), ah2 = pack2b(f0.z, f0.w);
            uint32_t ah1 = pack2b(f1.x, f1.y), ah3 = pack2b(f1.z, f1.w);
            uint32_t al0 = lo_resb(ah0, f0.x, f0.y), al2 = lo_resb(ah2, f0.z, f0.w);
            uint32_t al1 = lo_resb(ah1, f1.x, f1.y), al3 = lo_resb(ah3, f1.z, f1.w);
#pragma unroll
            for (int nt = 0; nt < 4; nt++) {
                const uint4 q = *(const uint4*)&sw[(nt * 8 + gid) * S_X + kt * 16 + tig * 4];
                mma16b(acc[nt], ah0, ah1, ah2, ah3, q.x, q.y);
                mma16b(acc[nt], ah0, ah1, ah2, ah3, q.z, q.w);
                mma16b(acc[nt], al0, al1, al2, al3, q.x, q.y);
            }
        }
        float* gp = d_G + (size_t)u * TB * G4;
#pragma unroll
        for (int nt = 0; nt < 4; nt++) {
            float* p0 = gp + (size_t)row0 * G4 + gb + nt * 8 + tig * 2;
            float* p1 = gp + (size_t)row1 * G4 + gb + nt * 8 + tig * 2;
            *(float2*)p0 = make_float2(acc[nt][0], acc[nt][1]);
            *(float2*)p1 = make_float2(acc[nt][2], acc[nt][3]);
        }
    }
}

// ---------------- persistent 2D-LSTM kernel: split-phase dual GEMM ----------------
extern __shared__ uint32_t smw[];

__global__ void __launch_bounds__(THREADS, 1)
lstm2d_k(const float* __restrict__ W_ih, const float* __restrict__ W_hh,
         float* __restrict__ out) {
    const int tid  = threadIdx.x;
    const int lane = tid & 31;
    const int w    = tid >> 5;
    const int rg   = w & 1;             // 16-row group (producer role)
    const int kq   = w >> 1;            // K quarter: kt [8kq, 8kq+8)
    const int gid  = lane >> 2;
    const int tig  = lane & 3;
    const int bid  = blockIdx.x;
    const int j    = bid >> 1;          // gate-col block
    const int s    = bid & 1;           // batch half
    const int nb   = j * 8;
    const int prow0 = s * 32 + rg * 16 + gid;   // producer rows
    const int prow1 = prow0 + 8;
    const int ktb  = kq * 8;
    // epilogue mapping: one (row, col) cell per thread
    const int crow = tid >> 3;          // 0..31 CTA-local row
    const int ccol = tid & 7;           // 0..7 local n
    const int grow = s * 32 + crow;     // global batch row
    float* red  = (float*)(smw + OFF_RED);          // hh partials: [kq*4+gg][32][8]
    float* red2 = red + 4096;                        // ih partials

    // ---- weights -> smem fp16 pairs. region 0: W_hh; region 1: W_ih[:,48:560] ----
    for (int idx = tid; idx < 2 * 32 * 256; idx += THREADS) {
        const int region = idx >> 13;
        const int id2 = idx & 8191;
        const int cl = id2 >> 8, k0 = (id2 & 255) * 2;
        const int growt = (cl >> 3) * NCH + nb + (cl & 7);
        float w0, w1;
        if (region == 0) {
            w0 = W_hh[(size_t)growt * NCH + k0];
            w1 = W_hh[(size_t)growt * NCH + k0 + 1];
        } else {
            w0 = W_ih[(size_t)growt * K_IH + 48 + k0];
            w1 = W_ih[(size_t)growt * K_IH + 48 + k0 + 1];
        }
        int kt = k0 >> 4, r = k0 & 15;
        smw[region * OFF_WPRE + cl * S_W + kt * 8 + (r >> 2) * 2 + ((r >> 1) & 1)] = pack2h(w0, w1);
    }
    __syncthreads();

    float cst = 0.f;        // per-thread cell state for (grow, nb+ccol)
    float ga[4];            // per-thread G0 prefetch
    float rngv[4] = {0.f, 0.f, 0.f, 0.f};   // ring value for current step (prefetched)
#pragma unroll
    for (int gg = 0; gg < 4; gg++)
        ga[gg] = __ldcg(&d_G[(size_t)grow * G4 + gg * NCH + nb + ccol]);

    for (int t = 0; t < TSTEPS; t++) {
        // ---- poll own-half flags (64 producers, 1 thread each) ----
        if (t > 0 && tid < 64) {
            while (ld_acq(&d_h_done[(s * 64 + tid) * FPAD]) < t - 1) {}
        }
        __syncthreads();                // barrier A

        // ---- critical phase: hh GEMM only ----
        if (t > 0) {
            float ahh[4][4];
#pragma unroll
            for (int gg = 0; gg < 4; gg++)
#pragma unroll
                for (int i = 0; i < 4; i++) ahh[gg][i] = 0.f;

            uint4 A0[8], A1[8];
            const uint4* pq0 = d_Hq + ((size_t)(t - 1) * TB + prow0) * 128 + ktb * 4 + tig;
            const uint4* pq1 = d_Hq + ((size_t)(t - 1) * TB + prow1) * 128 + ktb * 4 + tig;
#pragma unroll
            for (int kt = 0; kt < 8; kt++) { A0[kt] = pq0[kt * 4]; A1[kt] = pq1[kt * 4]; }
#pragma unroll
            for (int kt = 0; kt < 8; kt++) {
#pragma unroll
                for (int gg = 0; gg < 4; gg++) {
                    const uint2 qh = *(const uint2*)&smw[(gg * 8 + gid) * S_W + (ktb + kt) * 8 + tig * 2];
                    mma16h(ahh[gg], A0[kt].x, A1[kt].x, A0[kt].y, A1[kt].y, qh.x, qh.y);
                    mma16h(ahh[gg], A0[kt].z, A1[kt].z, A0[kt].w, A1[kt].w, qh.x, qh.y);
                }
            }
#pragma unroll
            for (int gg = 0; gg < 4; gg++) {
                const int base = ((kq * 4 + gg) * 32 + (rg * 16 + gid)) * 8 + tig * 2;
                *(float2*)&red[base]      = make_float2(ahh[gg][0], ahh[gg][1]);
                *(float2*)&red[base + 64] = make_float2(ahh[gg][2], ahh[gg][3]);
            }
        }
        __syncthreads();                // barrier B

        // ---- parallel epilogue: each thread owns (crow, ccol) ----
        float sumh[4];
#pragma unroll
        for (int gg = 0; gg < 4; gg++) sumh[gg] = ga[gg] + rngv[gg];
        if (t > 0) {
#pragma unroll
            for (int q = 0; q < 4; q++)
#pragma unroll
                for (int gg = 0; gg < 4; gg++)
                    sumh[gg] += red[((q * 4 + gg) * 32 + crow) * 8 + ccol];
        }

        float cc = sigm(sumh[1]) * cst + sigm(sumh[0]) * tanh_f(sumh[2]);
        cst = cc;
        float h = sigm(sumh[3]) * tanh_f(cc);

        // pack + publish d_Hq (only piece needed before release)
        {
            float a = __shfl_xor_sync(0xffffffffu, h, 1);
            float e0 = (ccol & 1) ? a : h;
            float e1 = (ccol & 1) ? h : a;
            uint32_t hpair = pack2h(e0, e1);
            uint32_t lpair = lo_resh(hpair, e0, e1);
            uint32_t hpair2 = __shfl_xor_sync(0xffffffffu, hpair, 2);
            uint32_t lpair2 = __shfl_xor_sync(0xffffffffu, lpair, 2);
            if ((ccol & 3) == 0) {
                d_Hq[((size_t)t * TB + grow) * 128 + j * 2 + (ccol >> 2)] =
                    make_uint4(hpair, hpair2, lpair, lpair2);
            }
        }
        __syncthreads();                // barrier C: all d_Hq stores issued
        if (tid == 0) st_rel(&d_h_done[(s * 64 + j) * FPAD], t);

        // ================= tail phase (off the inter-CTA chain) =================
        out[(size_t)grow * HSTRIDE + (size_t)t * NCH + nb + ccol] = h;

        // ih GEMM: A re-loaded from L1 (hot lines), fused per-kt
        if (t > 0) {
            float aih[4][4];
#pragma unroll
            for (int gg = 0; gg < 4; gg++)
#pragma unroll
                for (int i = 0; i < 4; i++) aih[gg][i] = 0.f;
            const uint4* pq0 = d_Hq + ((size_t)(t - 1) * TB + prow0) * 128 + ktb * 4 + tig;
            const uint4* pq1 = d_Hq + ((size_t)(t - 1) * TB + prow1) * 128 + ktb * 4 + tig;
#pragma unroll
            for (int kt = 0; kt < 8; kt++) {
                uint4 A0 = pq0[kt * 4];
                uint4 A1 = pq1[kt * 4];
#pragma unroll
                for (int gg = 0; gg < 4; gg++) {
                    const uint2 qi = *(const uint2*)&smw[OFF_WPRE + (gg * 8 + gid) * S_W + (ktb + kt) * 8 + tig * 2];
                    mma16h(aih[gg], A0.x, A1.x, A0.y, A1.y, qi.x, qi.y);
                    mma16h(aih[gg], A0.z, A1.z, A0.w, A1.w, qi.x, qi.y);
                }
            }
#pragma unroll
            for (int gg = 0; gg < 4; gg++) {
                const int base = ((kq * 4 + gg) * 32 + (rg * 16 + gid)) * 8 + tig * 2;
                *(float2*)&red2[base]      = make_float2(aih[gg][0], aih[gg][1]);
                *(float2*)&red2[base + 64] = make_float2(aih[gg][2], aih[gg][3]);
            }
        }
        __syncthreads();                // barrier D (tail)

        if (t > 0) {
            float sumi[4] = {0.f, 0.f, 0.f, 0.f};
#pragma unroll
            for (int q = 0; q < 4; q++)
#pragma unroll
                for (int gg = 0; gg < 4; gg++)
                    sumi[gg] += red2[((q * 4 + gg) * 32 + crow) * 8 + ccol];
            float* wp = d_R + ((size_t)bid * RSL + ((t + 31) & (RSL - 1))) * 1024;
#pragma unroll
            for (int gg = 0; gg < 4; gg++) wp[(gg * 32 + crow) * 8 + ccol] = sumi[gg];
        }

        // prefetch ring value + G0 for step t+1
        {
            const int tp = t + 1;
            if (tp >= 32 && tp < TSTEPS) {
                const float* rp = d_R + ((size_t)bid * RSL + (tp & (RSL - 1))) * 1024;
#pragma unroll
                for (int gg = 0; gg < 4; gg++) rngv[gg] = __ldcg(&rp[(gg * 32 + crow) * 8 + ccol]);
            } else {
#pragma unroll
                for (int gg = 0; gg < 4; gg++) rngv[gg] = 0.f;
            }
            const int tn = (tp < TSTEPS) ? tp : TSTEPS - 1;
#pragma unroll
            for (int gg = 0; gg < 4; gg++)
                ga[gg] = __ldcg(&d_G[((size_t)tn * TB + grow) * G4 + gg * NCH + nb + ccol]);
        }
    }
}

// ---------------- launch ----------------
extern "C" void kernel_launch(void* const* d_in, const int* in_sizes, int n_in,
                              void* d_out, int out_size) {
    const float* batch = (const float*)d_in[0];
    const float* W_ih  = (const float*)d_in[1];
    const float* W_hh  = (const float*)d_in[2];
    const float* b_ih  = (const float*)d_in[3];
    const float* b_hh  = (const float*)d_in[4];
    float* out = (float*)d_out;

    const int smem = SMEM_WORDS * 4;   // (16896 + 8192) * 4 = 100352 B
    cudaFuncSetAttribute(lstm2d_k, cudaFuncAttributeMaxDynamicSharedMemorySize, smem);

    init_k<<<16, 256>>>();
    xc_k<<<dim3(64, 16), 128>>>(batch, W_ih, b_ih, b_hh);
    lstm2d_k<<<NCTA, THREADS, smem>>>(W_ih, W_hh, out);
}

// round 16
// speedup vs baseline: 1.1807x; 1.1807x over previous
#include <cuda_runtime.h>
#include <cuda_bf16.h>
#include <cuda_fp16.h>
#include <cstdint>

// ---------------- problem constants ----------------
#define TB      64          // batch
#define NCH     512         // hidden cells
#define TSTEPS  1024        // SY*SX
#define G4      2048        // 4*NCH gate columns
#define K_IH    560         // 48 + NCH
#define NCTA    128         // CTA (j,s): j = gate-col block (64), s = batch half (2)
#define THREADS 256         // 8 warps: rg=w&1 (16-row group), kq=w>>1 (K quarter)
#define HSTRIDE ((size_t)TSTEPS * NCH)
#define S_W     264         // smem words/col, fp16 pairs (==8 mod 32 -> conflict-free LDS.64)
#define S_X     48          // xc_k smem words/col
#define FPAD    32          // ints per flag: one 128B line each
#define RSL     32          // CTA-private ring slots
#define OFF_WPRE (32 * S_W)         // word offset: W_ihh weights
#define OFF_RED  (64 * S_W)         // word offset: partials (2 sets x 4096 floats)
#define SMEM_WORDS (OFF_RED + 8192)

// ---------------- device scratch (static: allocation-free) ----------------
__device__ float d_G[(size_t)TSTEPS * TB * G4];        // xc_k output (x@W_ihx + bias), 512 MB
__device__ uint2 d_Hq[(size_t)TSTEPS * TB * 128];      // h fp16 {pair(n0,n1), pair(n2,n3)}, 64 MB
__device__ float d_R[(size_t)NCTA * RSL * 1024];       // CTA-private look-ahead rings, 16 MB
__device__ int   d_h_done[NCTA * FPAD];                // flag (s*64 + j)

// ---------------- bf16 helpers (xc_k only) ----------------
__device__ __forceinline__ uint32_t pack2b(float e0, float e1) {
    uint32_t d;
    asm("cvt.rn.bf16x2.f32 %0, %1, %2;" : "=r"(d) : "f"(e1), "f"(e0));
    return d;
}
__device__ __forceinline__ uint32_t lo_resb(uint32_t hp, float e0, float e1) {
    float h0 = __uint_as_float(hp << 16);
    float h1 = __uint_as_float(hp & 0xFFFF0000u);
    return pack2b(e0 - h0, e1 - h1);
}
__device__ __forceinline__ void mma16b(float* c,
                                       uint32_t a0, uint32_t a1, uint32_t a2, uint32_t a3,
                                       uint32_t b0, uint32_t b1) {
    asm volatile(
        "mma.sync.aligned.m16n8k16.row.col.f32.bf16.bf16.f32 "
        "{%0,%1,%2,%3},{%4,%5,%6,%7},{%8,%9},{%0,%1,%2,%3};"
        : "+f"(c[0]), "+f"(c[1]), "+f"(c[2]), "+f"(c[3])
        : "r"(a0), "r"(a1), "r"(a2), "r"(a3), "r"(b0), "r"(b1));
}

// ---------------- fp16 helpers ----------------
__device__ __forceinline__ uint32_t pack2h(float e0, float e1) {
    uint32_t d;
    asm("cvt.rn.f16x2.f32 %0, %1, %2;" : "=r"(d) : "f"(e1), "f"(e0));
    return d;
}
__device__ __forceinline__ void mma16h(float* c,
                                       uint32_t a0, uint32_t a1, uint32_t a2, uint32_t a3,
                                       uint32_t b0, uint32_t b1) {
    asm volatile(
        "mma.sync.aligned.m16n8k16.row.col.f32.f16.f16.f32 "
        "{%0,%1,%2,%3},{%4,%5,%6,%7},{%8,%9},{%0,%1,%2,%3};"
        : "+f"(c[0]), "+f"(c[1]), "+f"(c[2]), "+f"(c[3])
        : "r"(a0), "r"(a1), "r"(a2), "r"(a3), "r"(b0), "r"(b1));
}

__device__ __forceinline__ int ld_acq(const int* p) {
    int v;
    asm volatile("ld.acquire.gpu.global.b32 %0, [%1];" : "=r"(v) : "l"(p) : "memory");
    return v;
}
__device__ __forceinline__ void st_rel(int* p, int v) {
    asm volatile("st.release.gpu.global.b32 [%0], %1;" :: "l"(p), "r"(v) : "memory");
}
__device__ __forceinline__ float sigm(float x)  { return 1.0f / (1.0f + __expf(-x)); }
__device__ __forceinline__ float tanh_f(float x){ return 1.0f - 2.0f / (__expf(2.0f * x) + 1.0f); }

// ---------------- init (graph-replay safe) ----------------
__global__ void init_k() {
    int i = blockIdx.x * blockDim.x + threadIdx.x;
    if (i < NCTA * FPAD) d_h_done[i] = -1;
}

// ---------------- Xc precompute: G0[t] = bias + x_t @ W_ih[:, :48]^T ----------------
__global__ void __launch_bounds__(128)
xc_k(const float* __restrict__ batch, const float* __restrict__ W_ih,
     const float* __restrict__ b_ih, const float* __restrict__ b_hh) {
    __shared__ uint32_t sw[32 * S_X];
    const int tid = threadIdx.x;
    const int lane = tid & 31, w = tid >> 5;
    const int gid = lane >> 2, tig = lane & 3;
    const int row0 = w * 16 + gid, row1 = row0 + 8;
    const int gb = blockIdx.x * 32;

    for (int idx = tid; idx < 32 * 24; idx += 128) {
        int cl = idx / 24, k0 = (idx - cl * 24) * 2;
        float w0 = W_ih[(size_t)(gb + cl) * K_IH + k0];
        float w1 = W_ih[(size_t)(gb + cl) * K_IH + k0 + 1];
        uint32_t hi = pack2b(w0, w1);
        int kt = k0 >> 4, r = k0 & 15;
        int pos = cl * S_X + kt * 16 + (r >> 2) * 4 + ((r >> 1) & 1);
        sw[pos] = hi; sw[pos + 2] = lo_resb(hi, w0, w1);
    }
    __syncthreads();

    float bias[4][2];
#pragma unroll
    for (int nt = 0; nt < 4; nt++) {
        int g = gb + nt * 8 + tig * 2;
        bias[nt][0] = b_ih[g] + b_hh[g];
        bias[nt][1] = b_ih[g + 1] + b_hh[g + 1];
    }

    for (int us = 0; us < 64; us++) {
        const int u = blockIdx.y * 64 + us;
        const int i = u >> 5, j = u & 31;
        float acc[4][4];
#pragma unroll
        for (int nt = 0; nt < 4; nt++) {
            acc[nt][0] = bias[nt][0]; acc[nt][1] = bias[nt][1];
            acc[nt][2] = bias[nt][0]; acc[nt][3] = bias[nt][1];
        }
#pragma unroll
        for (int kt = 0; kt < 3; kt++) {
            float4 f0 = *(const float4*)&batch[(((size_t)row0 * 3 + kt) * 128 + i * 4 + tig) * 128 + j * 4];
            float4 f1 = *(const float4*)&batch[(((size_t)row1 * 3 + kt) * 128 + i * 4 + tig) * 128 + j * 4];
            uint32_t ah0 = pack2b(f0.x, f0.y), ah2 = pack2b(f0.z, f0.w);
            uint32_t ah1 = pack2b(f1.x, f1.y), ah3 = pack2b(f1.z, f1.w);
            uint32_t al0 = lo_resb(ah0, f0.x, f0.y), al2 = lo_resb(ah2, f0.z, f0.w);
            uint32_t al1 = lo_resb(ah1, f1.x, f1.y), al3 = lo_resb(ah3, f1.z, f1.w);
#pragma unroll
            for (int nt = 0; nt < 4; nt++) {
                const uint4 q = *(const uint4*)&sw[(nt * 8 + gid) * S_X + kt * 16 + tig * 4];
                mma16b(acc[nt], ah0, ah1, ah2, ah3, q.x, q.y);
                mma16b(acc[nt], ah0, ah1, ah2, ah3, q.z, q.w);
                mma16b(acc[nt], al0, al1, al2, al3, q.x, q.y);
            }
        }
        float* gp = d_G + (size_t)u * TB * G4;
#pragma unroll
        for (int nt = 0; nt < 4; nt++) {
            float* p0 = gp + (size_t)row0 * G4 + gb + nt * 8 + tig * 2;
            float* p1 = gp + (size_t)row1 * G4 + gb + nt * 8 + tig * 2;
            *(float2*)p0 = make_float2(acc[nt][0], acc[nt][1]);
            *(float2*)p1 = make_float2(acc[nt][2], acc[nt][3]);
        }
    }
}

// ---------------- persistent 2D-LSTM kernel: fused dual GEMM, pure fp16 ----------------
extern __shared__ uint32_t smw[];

__global__ void __launch_bounds__(THREADS, 1)
lstm2d_k(const float* __restrict__ W_ih, const float* __restrict__ W_hh,
         float* __restrict__ out) {
    const int tid  = threadIdx.x;
    const int lane = tid & 31;
    const int w    = tid >> 5;
    const int rg   = w & 1;             // 16-row group (producer role)
    const int kq   = w >> 1;            // K quarter: kt [8kq, 8kq+8)
    const int gid  = lane >> 2;
    const int tig  = lane & 3;
    const int bid  = blockIdx.x;
    const int j    = bid >> 1;          // gate-col block
    const int s    = bid & 1;           // batch half
    const int nb   = j * 8;
    const int prow0 = s * 32 + rg * 16 + gid;   // producer rows
    const int prow1 = prow0 + 8;
    const int ktb  = kq * 8;
    // epilogue mapping: one (row, col) cell per thread
    const int crow = tid >> 3;          // 0..31 CTA-local row
    const int ccol = tid & 7;           // 0..7 local n
    const int grow = s * 32 + crow;     // global batch row
    float* red  = (float*)(smw + OFF_RED);          // hh partials: [kq*4+gg][32][8]
    float* red2 = red + 4096;                        // ih partials

    // ---- weights -> smem fp16 pairs. region 0: W_hh; region 1: W_ih[:,48:560] ----
    for (int idx = tid; idx < 2 * 32 * 256; idx += THREADS) {
        const int region = idx >> 13;
        const int id2 = idx & 8191;
        const int cl = id2 >> 8, k0 = (id2 & 255) * 2;
        const int growt = (cl >> 3) * NCH + nb + (cl & 7);
        float w0, w1;
        if (region == 0) {
            w0 = W_hh[(size_t)growt * NCH + k0];
            w1 = W_hh[(size_t)growt * NCH + k0 + 1];
        } else {
            w0 = W_ih[(size_t)growt * K_IH + 48 + k0];
            w1 = W_ih[(size_t)growt * K_IH + 48 + k0 + 1];
        }
        int kt = k0 >> 4, r = k0 & 15;
        smw[region * OFF_WPRE + cl * S_W + kt * 8 + (r >> 2) * 2 + ((r >> 1) & 1)] = pack2h(w0, w1);
    }
    __syncthreads();

    float cst = 0.f;        // per-thread cell state for (grow, nb+ccol)
    float ga[4];            // per-thread G0 prefetch
    float rngv[4] = {0.f, 0.f, 0.f, 0.f};   // ring value for current step (prefetched)
#pragma unroll
    for (int gg = 0; gg < 4; gg++)
        ga[gg] = __ldcg(&d_G[(size_t)grow * G4 + gg * NCH + nb + ccol]);

    for (int t = 0; t < TSTEPS; t++) {
        // ---- poll own-half flags (64 producers, 1 thread each) ----
        if (t > 0 && tid < 64) {
            while (ld_acq(&d_h_done[(s * 64 + tid) * FPAD]) < t - 1) {}
        }
        __syncthreads();                // barrier A

        // ---- fused dual GEMM (hh + ih), single fp16 pass each ----
        if (t > 0) {
            float ahh[4][4], aih[4][4];
#pragma unroll
            for (int gg = 0; gg < 4; gg++)
#pragma unroll
                for (int i = 0; i < 4; i++) { ahh[gg][i] = 0.f; aih[gg][i] = 0.f; }

            // front-batched A loads: 8 kt x 2 rows (uint2 each)
            uint2 A0[8], A1[8];
            const uint2* pq0 = d_Hq + ((size_t)(t - 1) * TB + prow0) * 128 + ktb * 4 + tig;
            const uint2* pq1 = d_Hq + ((size_t)(t - 1) * TB + prow1) * 128 + ktb * 4 + tig;
#pragma unroll
            for (int kt = 0; kt < 8; kt++) { A0[kt] = pq0[kt * 4]; A1[kt] = pq1[kt * 4]; }
#pragma unroll
            for (int kt = 0; kt < 8; kt++) {
#pragma unroll
                for (int gg = 0; gg < 4; gg++) {
                    const int wof = (gg * 8 + gid) * S_W + (ktb + kt) * 8 + tig * 2;
                    const uint2 qh = *(const uint2*)&smw[wof];
                    const uint2 qi = *(const uint2*)&smw[OFF_WPRE + wof];
                    mma16h(ahh[gg], A0[kt].x, A1[kt].x, A0[kt].y, A1[kt].y, qh.x, qh.y);
                    mma16h(aih[gg], A0[kt].x, A1[kt].x, A0[kt].y, A1[kt].y, qi.x, qi.y);
                }
            }

            // write partials: [kq*4+gg][lrow][col]
#pragma unroll
            for (int gg = 0; gg < 4; gg++) {
                const int base = ((kq * 4 + gg) * 32 + (rg * 16 + gid)) * 8 + tig * 2;
                *(float2*)&red[base]       = make_float2(ahh[gg][0], ahh[gg][1]);
                *(float2*)&red[base + 64]  = make_float2(ahh[gg][2], ahh[gg][3]);
                *(float2*)&red2[base]      = make_float2(aih[gg][0], aih[gg][1]);
                *(float2*)&red2[base + 64] = make_float2(aih[gg][2], aih[gg][3]);
            }
        }
        __syncthreads();                // barrier B

        // ---- parallel epilogue: each thread owns (crow, ccol) ----
        float sumh[4], sumi[4];
#pragma unroll
        for (int gg = 0; gg < 4; gg++) { sumh[gg] = ga[gg] + rngv[gg]; sumi[gg] = 0.f; }
        if (t > 0) {
#pragma unroll
            for (int q = 0; q < 4; q++)
#pragma unroll
                for (int gg = 0; gg < 4; gg++) {
                    const int a = ((q * 4 + gg) * 32 + crow) * 8 + ccol;
                    sumh[gg] += red[a];
                    sumi[gg] += red2[a];
                }
        }

        // activations (i,f,g,o)
        float cc = sigm(sumh[1]) * cst + sigm(sumh[0]) * tanh_f(sumh[2]);
        cst = cc;
        float h = sigm(sumh[3]) * tanh_f(cc);

        // pack + publish d_Hq (only piece needed before release)
        {
            float a = __shfl_xor_sync(0xffffffffu, h, 1);
            float e0 = (ccol & 1) ? a : h;
            float e1 = (ccol & 1) ? h : a;
            uint32_t hpair = pack2h(e0, e1);
            uint32_t hpair2 = __shfl_xor_sync(0xffffffffu, hpair, 2);
            if ((ccol & 3) == 0) {
                d_Hq[((size_t)t * TB + grow) * 128 + j * 2 + (ccol >> 2)] =
                    make_uint2(hpair, hpair2);
            }
        }
        __syncthreads();                // barrier C: all d_Hq stores issued
        if (tid == 0) st_rel(&d_h_done[(s * 64 + j) * FPAD], t);

        // ---- off-critical-path: out store, ring store, prefetches ----
        out[(size_t)grow * HSTRIDE + (size_t)t * NCH + nb + ccol] = h;
        if (t > 0) {
            float* wp = d_R + ((size_t)bid * RSL + ((t + 31) & (RSL - 1))) * 1024;
#pragma unroll
            for (int gg = 0; gg < 4; gg++) wp[(gg * 32 + crow) * 8 + ccol] = sumi[gg];
        }
        {
            const int tp = t + 1;
            if (tp >= 32 && tp < TSTEPS) {   // ring slot tp written at step tp-31 <= t-30: long done
                const float* rp = d_R + ((size_t)bid * RSL + (tp & (RSL - 1))) * 1024;
#pragma unroll
                for (int gg = 0; gg < 4; gg++) rngv[gg] = __ldcg(&rp[(gg * 32 + crow) * 8 + ccol]);
            } else {
#pragma unroll
                for (int gg = 0; gg < 4; gg++) rngv[gg] = 0.f;
            }
            const int tn = (tp < TSTEPS) ? tp : TSTEPS - 1;
#pragma unroll
            for (int gg = 0; gg < 4; gg++)
                ga[gg] = __ldcg(&d_G[((size_t)tn * TB + grow) * G4 + gg * NCH + nb + ccol]);
        }
    }
}

// ---------------- launch ----------------
extern "C" void kernel_launch(void* const* d_in, const int* in_sizes, int n_in,
                              void* d_out, int out_size) {
    const float* batch = (const float*)d_in[0];
    const float* W_ih  = (const float*)d_in[1];
    const float* W_hh  = (const float*)d_in[2];
    const float* b_ih  = (const float*)d_in[3];
    const float* b_hh  = (const float*)d_in[4];
    float* out = (float*)d_out;

    const int smem = SMEM_WORDS * 4;   // (16896 + 8192) * 4 = 100352 B
    cudaFuncSetAttribute(lstm2d_k, cudaFuncAttributeMaxDynamicSharedMemorySize, smem);

    init_k<<<16, 256>>>();
    xc_k<<<dim3(64, 16), 128>>>(batch, W_ih, b_ih, b_hh);
    lstm2d_k<<<NCTA, THREADS, smem>>>(W_ih, W_hh, out);
}

// round 17
// speedup vs baseline: 1.3336x; 1.1296x over previous
#include <cuda_runtime.h>
#include <cuda_bf16.h>
#include <cuda_fp16.h>
#include <cstdint>

// ---------------- problem constants ----------------
#define TB      64          // batch
#define NCH     512         // hidden cells
#define TSTEPS  1024        // SY*SX
#define G4      2048        // 4*NCH gate columns
#define K_IH    560         // 48 + NCH
#define NCTA    128         // CTA (j,s): j = gate-col block (64), s = batch half (2)
#define THREADS 256         // 8 warps: rg=w&1 (16-row group), kq=w>>1 (K quarter)
#define HSTRIDE ((size_t)TSTEPS * NCH)
#define S_W     264         // smem words/col, fp16 pairs (==8 mod 32 -> conflict-free LDS.64)
#define S_X     48          // xc_k smem words/col
#define FPAD    32          // ints per flag: one 128B line each
#define RSL     32          // CTA-private ring slots
#define OFF_WPRE (32 * S_W)         // word offset: W_ihh weights
#define OFF_RED  (64 * S_W)         // word offset: partials (2 sets x 4096 floats)
#define SMEM_WORDS (OFF_RED + 8192)

// ---------------- device scratch (static: allocation-free) ----------------
__device__ float d_G[(size_t)TSTEPS * TB * G4];        // xc_k output (x@W_ihx + bias), 512 MB
__device__ uint2 d_Hq[(size_t)TSTEPS * TB * 128];      // h fp16 {pair(n0,n1), pair(n2,n3)}, 64 MB
__device__ float d_R[(size_t)NCTA * RSL * 1024];       // CTA-private look-ahead rings, 16 MB
__device__ int   d_h_done[NCTA * FPAD];                // flag (s*64 + j)

// ---------------- bf16 helpers (xc_k only) ----------------
__device__ __forceinline__ uint32_t pack2b(float e0, float e1) {
    uint32_t d;
    asm("cvt.rn.bf16x2.f32 %0, %1, %2;" : "=r"(d) : "f"(e1), "f"(e0));
    return d;
}
__device__ __forceinline__ uint32_t lo_resb(uint32_t hp, float e0, float e1) {
    float h0 = __uint_as_float(hp << 16);
    float h1 = __uint_as_float(hp & 0xFFFF0000u);
    return pack2b(e0 - h0, e1 - h1);
}
__device__ __forceinline__ void mma16b(float* c,
                                       uint32_t a0, uint32_t a1, uint32_t a2, uint32_t a3,
                                       uint32_t b0, uint32_t b1) {
    asm volatile(
        "mma.sync.aligned.m16n8k16.row.col.f32.bf16.bf16.f32 "
        "{%0,%1,%2,%3},{%4,%5,%6,%7},{%8,%9},{%0,%1,%2,%3};"
        : "+f"(c[0]), "+f"(c[1]), "+f"(c[2]), "+f"(c[3])
        : "r"(a0), "r"(a1), "r"(a2), "r"(a3), "r"(b0), "r"(b1));
}

// ---------------- fp16 helpers ----------------
__device__ __forceinline__ uint32_t pack2h(float e0, float e1) {
    uint32_t d;
    asm("cvt.rn.f16x2.f32 %0, %1, %2;" : "=r"(d) : "f"(e1), "f"(e0));
    return d;
}
__device__ __forceinline__ void mma16h(float* c,
                                       uint32_t a0, uint32_t a1, uint32_t a2, uint32_t a3,
                                       uint32_t b0, uint32_t b1) {
    asm volatile(
        "mma.sync.aligned.m16n8k16.row.col.f32.f16.f16.f32 "
        "{%0,%1,%2,%3},{%4,%5,%6,%7},{%8,%9},{%0,%1,%2,%3};"
        : "+f"(c[0]), "+f"(c[1]), "+f"(c[2]), "+f"(c[3])
        : "r"(a0), "r"(a1), "r"(a2), "r"(a3), "r"(b0), "r"(b1));
}

__device__ __forceinline__ int ld_acq(const int* p) {
    int v;
    asm volatile("ld.acquire.gpu.global.b32 %0, [%1];" : "=r"(v) : "l"(p) : "memory");
    return v;
}
__device__ __forceinline__ void st_rel(int* p, int v) {
    asm volatile("st.release.gpu.global.b32 [%0], %1;" :: "l"(p), "r"(v) : "memory");
}
__device__ __forceinline__ float sigm(float x)  { return 1.0f / (1.0f + __expf(-x)); }
__device__ __forceinline__ float tanh_f(float x){ return 1.0f - 2.0f / (__expf(2.0f * x) + 1.0f); }

// ---------------- init (graph-replay safe) ----------------
__global__ void init_k() {
    int i = blockIdx.x * blockDim.x + threadIdx.x;
    if (i < NCTA * FPAD) d_h_done[i] = -1;
}

// ---------------- Xc precompute: G0[t] = bias + x_t @ W_ih[:, :48]^T ----------------
__global__ void __launch_bounds__(128)
xc_k(const float* __restrict__ batch, const float* __restrict__ W_ih,
     const float* __restrict__ b_ih, const float* __restrict__ b_hh) {
    __shared__ uint32_t sw[32 * S_X];
    const int tid = threadIdx.x;
    const int lane = tid & 31, w = tid >> 5;
    const int gid = lane >> 2, tig = lane & 3;
    const int row0 = w * 16 + gid, row1 = row0 + 8;
    const int gb = blockIdx.x * 32;

    for (int idx = tid; idx < 32 * 24; idx += 128) {
        int cl = idx / 24, k0 = (idx - cl * 24) * 2;
        float w0 = W_ih[(size_t)(gb + cl) * K_IH + k0];
        float w1 = W_ih[(size_t)(gb + cl) * K_IH + k0 + 1];
        uint32_t hi = pack2b(w0, w1);
        int kt = k0 >> 4, r = k0 & 15;
        int pos = cl * S_X + kt * 16 + (r >> 2) * 4 + ((r >> 1) & 1);
        sw[pos] = hi; sw[pos + 2] = lo_resb(hi, w0, w1);
    }
    __syncthreads();

    float bias[4][2];
#pragma unroll
    for (int nt = 0; nt < 4; nt++) {
        int g = gb + nt * 8 + tig * 2;
        bias[nt][0] = b_ih[g] + b_hh[g];
        bias[nt][1] = b_ih[g + 1] + b_hh[g + 1];
    }

    for (int us = 0; us < 64; us++) {
        const int u = blockIdx.y * 64 + us;
        const int i = u >> 5, j = u & 31;
        float acc[4][4];
#pragma unroll
        for (int nt = 0; nt < 4; nt++) {
            acc[nt][0] = bias[nt][0]; acc[nt][1] = bias[nt][1];
            acc[nt][2] = bias[nt][0]; acc[nt][3] = bias[nt][1];
        }
#pragma unroll
        for (int kt = 0; kt < 3; kt++) {
            float4 f0 = *(const float4*)&batch[(((size_t)row0 * 3 + kt) * 128 + i * 4 + tig) * 128 + j * 4];
            float4 f1 = *(const float4*)&batch[(((size_t)row1 * 3 + kt) * 128 + i * 4 + tig) * 128 + j * 4];
            uint32_t ah0 = pack2b(f0.x, f0.y), ah2 = pack2b(f0.z, f0.w);
            uint32_t ah1 = pack2b(f1.x, f1.y), ah3 = pack2b(f1.z, f1.w);
            uint32_t al0 = lo_resb(ah0, f0.x, f0.y), al2 = lo_resb(ah2, f0.z, f0.w);
            uint32_t al1 = lo_resb(ah1, f1.x, f1.y), al3 = lo_resb(ah3, f1.z, f1.w);
#pragma unroll
            for (int nt = 0; nt < 4; nt++) {
                const uint4 q = *(const uint4*)&sw[(nt * 8 + gid) * S_X + kt * 16 + tig * 4];
                mma16b(acc[nt], ah0, ah1, ah2, ah3, q.x, q.y);
                mma16b(acc[nt], ah0, ah1, ah2, ah3, q.z, q.w);
                mma16b(acc[nt], al0, al1, al2, al3, q.x, q.y);
            }
        }
        float* gp = d_G + (size_t)u * TB * G4;
#pragma unroll
        for (int nt = 0; nt < 4; nt++) {
            float* p0 = gp + (size_t)row0 * G4 + gb + nt * 8 + tig * 2;
            float* p1 = gp + (size_t)row1 * G4 + gb + nt * 8 + tig * 2;
            *(float2*)p0 = make_float2(acc[nt][0], acc[nt][1]);
            *(float2*)p1 = make_float2(acc[nt][2], acc[nt][3]);
        }
    }
}

// ---------------- persistent 2D-LSTM kernel: chunk-synced dual GEMM, fp16 ----------------
extern __shared__ uint32_t smw[];

__global__ void __launch_bounds__(THREADS, 1)
lstm2d_k(const float* __restrict__ W_ih, const float* __restrict__ W_hh,
         float* __restrict__ out) {
    const int tid  = threadIdx.x;
    const int lane = tid & 31;
    const int w    = tid >> 5;
    const int rg   = w & 1;             // 16-row group (producer role)
    const int kq   = w >> 1;            // K quarter: kt [8kq, 8kq+8)
    const int gid  = lane >> 2;
    const int tig  = lane & 3;
    const int bid  = blockIdx.x;
    const int j    = bid >> 1;          // gate-col block
    const int s    = bid & 1;           // batch half
    const int nb   = j * 8;
    const int prow0 = s * 32 + rg * 16 + gid;   // producer rows
    const int prow1 = prow0 + 8;
    const int ktb  = kq * 8;
    // epilogue mapping: one (row, col) cell per thread
    const int crow = tid >> 3;          // 0..31 CTA-local row
    const int ccol = tid & 7;           // 0..7 local n
    const int grow = s * 32 + crow;     // global batch row
    float* red  = (float*)(smw + OFF_RED);          // hh partials: [kq*4+gg][32][8]
    float* red2 = red + 4096;                        // ih partials
    // this warp's producer flag (lane < 16): producers j in [16kq, 16kq+16)
    const int* myflag = &d_h_done[(s * 64 + kq * 16 + (lane & 15)) * FPAD];

    // ---- weights -> smem fp16 pairs. region 0: W_hh; region 1: W_ih[:,48:560] ----
    for (int idx = tid; idx < 2 * 32 * 256; idx += THREADS) {
        const int region = idx >> 13;
        const int id2 = idx & 8191;
        const int cl = id2 >> 8, k0 = (id2 & 255) * 2;
        const int growt = (cl >> 3) * NCH + nb + (cl & 7);
        float w0, w1;
        if (region == 0) {
            w0 = W_hh[(size_t)growt * NCH + k0];
            w1 = W_hh[(size_t)growt * NCH + k0 + 1];
        } else {
            w0 = W_ih[(size_t)growt * K_IH + 48 + k0];
            w1 = W_ih[(size_t)growt * K_IH + 48 + k0 + 1];
        }
        int kt = k0 >> 4, r = k0 & 15;
        smw[region * OFF_WPRE + cl * S_W + kt * 8 + (r >> 2) * 2 + ((r >> 1) & 1)] = pack2h(w0, w1);
    }
    __syncthreads();

    float cst = 0.f;        // per-thread cell state for (grow, nb+ccol)
    float ga[4];            // per-thread G0 prefetch
    float rngv[4] = {0.f, 0.f, 0.f, 0.f};   // ring value for current step (prefetched)
#pragma unroll
    for (int gg = 0; gg < 4; gg++)
        ga[gg] = __ldcg(&d_G[(size_t)grow * G4 + gg * NCH + nb + ccol]);

    for (int t = 0; t < TSTEPS; t++) {
        // ---- chunk-local poll + fused dual GEMM (no CTA-wide pre-barrier) ----
        if (t > 0) {
            // each warp waits only for ITS 16 producers, then immediately works
            if (lane < 16) { while (ld_acq(myflag) < t - 1) {} }
            __syncwarp();

            float ahh[4][4], aih[4][4];
#pragma unroll
            for (int gg = 0; gg < 4; gg++)
#pragma unroll
                for (int i = 0; i < 4; i++) { ahh[gg][i] = 0.f; aih[gg][i] = 0.f; }

            // front-batched A loads: 8 kt x 2 rows (uint2 each)
            uint2 A0[8], A1[8];
            const uint2* pq0 = d_Hq + ((size_t)(t - 1) * TB + prow0) * 128 + ktb * 4 + tig;
            const uint2* pq1 = d_Hq + ((size_t)(t - 1) * TB + prow1) * 128 + ktb * 4 + tig;
#pragma unroll
            for (int kt = 0; kt < 8; kt++) { A0[kt] = pq0[kt * 4]; A1[kt] = pq1[kt * 4]; }
#pragma unroll
            for (int kt = 0; kt < 8; kt++) {
#pragma unroll
                for (int gg = 0; gg < 4; gg++) {
                    const int wof = (gg * 8 + gid) * S_W + (ktb + kt) * 8 + tig * 2;
                    const uint2 qh = *(const uint2*)&smw[wof];
                    const uint2 qi = *(const uint2*)&smw[OFF_WPRE + wof];
                    mma16h(ahh[gg], A0[kt].x, A1[kt].x, A0[kt].y, A1[kt].y, qh.x, qh.y);
                    mma16h(aih[gg], A0[kt].x, A1[kt].x, A0[kt].y, A1[kt].y, qi.x, qi.y);
                }
            }

            // write partials: [kq*4+gg][lrow][col]
#pragma unroll
            for (int gg = 0; gg < 4; gg++) {
                const int base = ((kq * 4 + gg) * 32 + (rg * 16 + gid)) * 8 + tig * 2;
                *(float2*)&red[base]       = make_float2(ahh[gg][0], ahh[gg][1]);
                *(float2*)&red[base + 64]  = make_float2(ahh[gg][2], ahh[gg][3]);
                *(float2*)&red2[base]      = make_float2(aih[gg][0], aih[gg][1]);
                *(float2*)&red2[base + 64] = make_float2(aih[gg][2], aih[gg][3]);
            }
        }
        __syncthreads();                // barrier B

        // ---- parallel epilogue: each thread owns (crow, ccol) ----
        float sumh[4], sumi[4];
#pragma unroll
        for (int gg = 0; gg < 4; gg++) { sumh[gg] = ga[gg] + rngv[gg]; sumi[gg] = 0.f; }
        if (t > 0) {
#pragma unroll
            for (int q = 0; q < 4; q++)
#pragma unroll
                for (int gg = 0; gg < 4; gg++) {
                    const int a = ((q * 4 + gg) * 32 + crow) * 8 + ccol;
                    sumh[gg] += red[a];
                    sumi[gg] += red2[a];
                }
        }

        // activations (i,f,g,o)
        float cc = sigm(sumh[1]) * cst + sigm(sumh[0]) * tanh_f(sumh[2]);
        cst = cc;
        float h = sigm(sumh[3]) * tanh_f(cc);

        // pack + publish d_Hq (only piece needed before release)
        {
            float a = __shfl_xor_sync(0xffffffffu, h, 1);
            float e0 = (ccol & 1) ? a : h;
            float e1 = (ccol & 1) ? h : a;
            uint32_t hpair = pack2h(e0, e1);
            uint32_t hpair2 = __shfl_xor_sync(0xffffffffu, hpair, 2);
            if ((ccol & 3) == 0) {
                d_Hq[((size_t)t * TB + grow) * 128 + j * 2 + (ccol >> 2)] =
                    make_uint2(hpair, hpair2);
            }
        }
        __syncthreads();                // barrier C: all d_Hq stores issued
        if (tid == 0) st_rel(&d_h_done[(s * 64 + j) * FPAD], t);

        // ---- off-critical-path: out store, ring store, prefetches ----
        out[(size_t)grow * HSTRIDE + (size_t)t * NCH + nb + ccol] = h;
        if (t > 0) {
            float* wp = d_R + ((size_t)bid * RSL + ((t + 31) & (RSL - 1))) * 1024;
#pragma unroll
            for (int gg = 0; gg < 4; gg++) wp[(gg * 32 + crow) * 8 + ccol] = sumi[gg];
        }
        {
            const int tp = t + 1;
            if (tp >= 32 && tp < TSTEPS) {   // ring slot tp written at step tp-31 <= t-30: long done
                const float* rp = d_R + ((size_t)bid * RSL + (tp & (RSL - 1))) * 1024;
#pragma unroll
                for (int gg = 0; gg < 4; gg++) rngv[gg] = __ldcg(&rp[(gg * 32 + crow) * 8 + ccol]);
            } else {
#pragma unroll
                for (int gg = 0; gg < 4; gg++) rngv[gg] = 0.f;
            }
            const int tn = (tp < TSTEPS) ? tp : TSTEPS - 1;
#pragma unroll
            for (int gg = 0; gg < 4; gg++)
                ga[gg] = __ldcg(&d_G[((size_t)tn * TB + grow) * G4 + gg * NCH + nb + ccol]);
        }
    }
}

// ---------------- launch ----------------
extern "C" void kernel_launch(void* const* d_in, const int* in_sizes, int n_in,
                              void* d_out, int out_size) {
    const float* batch = (const float*)d_in[0];
    const float* W_ih  = (const float*)d_in[1];
    const float* W_hh  = (const float*)d_in[2];
    const float* b_ih  = (const float*)d_in[3];
    const float* b_hh  = (const float*)d_in[4];
    float* out = (float*)d_out;

    const int smem = SMEM_WORDS * 4;   // (16896 + 8192) * 4 = 100352 B
    cudaFuncSetAttribute(lstm2d_k, cudaFuncAttributeMaxDynamicSharedMemorySize, smem);

    init_k<<<16, 256>>>();
    xc_k<<<dim3(64, 16), 128>>>(batch, W_ih, b_ih, b_hh);
    lstm2d_k<<<NCTA, THREADS, smem>>>(W_ih, W_hh, out);
}